// round 3
// baseline (speedup 1.0000x reference)
#include <cuda_runtime.h>

#define N_NODES 50000
#define N_EDGES 800000
#define NF 64
#define NG 64
#define NC 10

// ---- scratch (static __device__, no runtime allocation) ----
__device__ float g_deg[N_NODES];
__device__ float g_dis[N_NODES];
__device__ int   g_ecnt[N_NODES];
__device__ int   g_off[N_NODES + 1];
__device__ int   g_cur[N_NODES];
__device__ int   g_erow[N_EDGES];
__device__ float g_enrm[N_EDGES];
__device__ __align__(256) float g_A[N_NODES * NF];
__device__ __align__(256) float g_B[N_NODES * NF];
__device__ float g_pool[NG * NF];
__device__ float g_gcnt[NG];

// ---------------------------------------------------------------------------
__global__ void k_init() {
    int i = blockIdx.x * blockDim.x + threadIdx.x;
    if (i < N_NODES) { g_deg[i] = 1.0f; g_ecnt[i] = 0; }   // self-loop weight 1
    if (i < NG * NF) g_pool[i] = 0.0f;
    if (i < NG)      g_gcnt[i] = 0.0f;
}

// degree accumulation (sigmoid edge weights) + in-degree histogram
__global__ void k_deg(const int* __restrict__ col, const float* __restrict__ P) {
    int e = blockIdx.x * blockDim.x + threadIdx.x;
    if (e >= N_EDGES) return;
    float w = 1.0f / (1.0f + expf(-P[e]));
    int c = col[e];
    atomicAdd(&g_deg[c], w);
    atomicAdd(&g_ecnt[c], 1);
}

__global__ void k_dis() {
    int i = blockIdx.x * blockDim.x + threadIdx.x;
    if (i < N_NODES) g_dis[i] = rsqrtf(g_deg[i]);   // deg >= 1 always
}

// single-block exclusive scan of g_ecnt -> g_off (and cursor copy)
__global__ void k_scan() {
    __shared__ int sums[1024];
    int t = threadIdx.x;
    const int chunk = (N_NODES + 1023) / 1024;       // 49
    int s0 = t * chunk;
    int s1 = min(s0 + chunk, N_NODES);
    int local = 0;
    for (int i = s0; i < s1; i++) local += g_ecnt[i];
    sums[t] = local;
    __syncthreads();
    for (int d = 1; d < 1024; d <<= 1) {
        int add = (t >= d) ? sums[t - d] : 0;
        __syncthreads();
        sums[t] += add;
        __syncthreads();
    }
    int run = (t > 0) ? sums[t - 1] : 0;
    for (int i = s0; i < s1; i++) {
        g_off[i] = run;
        g_cur[i] = run;
        run += g_ecnt[i];
    }
    if (t == 1023) g_off[N_NODES] = sums[1023];
}

// fill CSC: per incoming edge store (source row, norm coefficient)
__global__ void k_fill(const int* __restrict__ row, const int* __restrict__ col,
                       const float* __restrict__ P) {
    int e = blockIdx.x * blockDim.x + threadIdx.x;
    if (e >= N_EDGES) return;
    int r = row[e], c = col[e];
    float w  = 1.0f / (1.0f + expf(-P[e]));
    float nm = g_dis[r] * w * g_dis[c];
    int slot = atomicAdd(&g_cur[c], 1);
    g_erow[slot] = r;
    g_enrm[slot] = nm;
}

// out[n,64] = in[n,64] @ W[64,64]; 64 rows per block, W staged in smem
__global__ void k_gemm(const float* __restrict__ in, const float* __restrict__ W,
                       float* __restrict__ out) {
    __shared__ float Ws[64][64];
    __shared__ float Is[4][64];
    int tx = threadIdx.x & 63;
    int ty = threadIdx.x >> 6;
    for (int i = threadIdx.x; i < 4096; i += 256)
        Ws[i >> 6][i & 63] = W[i];
    int base = blockIdx.x * 64;
    for (int rg = 0; rg < 16; rg++) {
        int r = base + rg * 4 + ty;
        float v = (r < N_NODES) ? in[r * 64 + tx] : 0.0f;
        __syncthreads();                 // also orders Ws writes before first use
        Is[ty][tx] = v;
        __syncthreads();
        float acc = 0.0f;
        #pragma unroll
        for (int k = 0; k < 64; k++)
            acc = fmaf(Is[ty][k], Ws[k][tx], acc);
        if (r < N_NODES) out[r * 64 + tx] = acc;
    }
}

// warp-per-node gather SpMM: B[c] = selfnorm*A[c] + sum_e norm_e * A[src_e] + bias
__global__ void k_agg(const float* __restrict__ A, float* __restrict__ B,
                      const float* __restrict__ bias, int do_relu) {
    int node = blockIdx.x * 8 + (threadIdx.x >> 5);
    if (node >= N_NODES) return;
    int lane = threadIdx.x & 31;
    const float2* Ar = (const float2*)A;

    float d  = g_dis[node];
    float sn = d * d;                     // self-loop coefficient
    float2 hv = __ldg(&Ar[node * 32 + lane]);
    float ax = sn * hv.x, ay = sn * hv.y;

    int s = g_off[node], e = g_off[node + 1];
    int i = s;
    int e4 = s + ((e - s) & ~3);
    for (; i < e4; i += 4) {              // 4x unroll for MLP across L2 latency
        int r0 = g_erow[i],   r1 = g_erow[i+1], r2 = g_erow[i+2], r3 = g_erow[i+3];
        float n0 = g_enrm[i], n1 = g_enrm[i+1], n2 = g_enrm[i+2], n3 = g_enrm[i+3];
        float2 h0 = __ldg(&Ar[r0 * 32 + lane]);
        float2 h1 = __ldg(&Ar[r1 * 32 + lane]);
        float2 h2 = __ldg(&Ar[r2 * 32 + lane]);
        float2 h3 = __ldg(&Ar[r3 * 32 + lane]);
        ax += n0 * h0.x + n1 * h1.x + n2 * h2.x + n3 * h3.x;
        ay += n0 * h0.y + n1 * h1.y + n2 * h2.y + n3 * h3.y;
    }
    for (; i < e; i++) {
        int r = g_erow[i];
        float nm = g_enrm[i];
        float2 h = __ldg(&Ar[r * 32 + lane]);
        ax += nm * h.x;
        ay += nm * h.y;
    }
    float2 bb = ((const float2*)bias)[lane];
    ax += bb.x; ay += bb.y;
    if (do_relu) { ax = fmaxf(ax, 0.0f); ay = fmaxf(ay, 0.0f); }
    ((float2*)B)[node * 32 + lane] = make_float2(ax, ay);
}

// segment mean pool: exploit sorted batch — run-length accumulate, few atomics
__global__ void k_pool(const float* __restrict__ B, const int* __restrict__ batch) {
    int tx = threadIdx.x;                  // 64 threads = 64 features
    int start = blockIdx.x * 512;
    if (start >= N_NODES) return;
    int end = min(start + 512, N_NODES);
    int cur = batch[start];
    float acc = 0.0f, c = 0.0f;
    for (int i = start; i < end; i++) {
        int g = batch[i];                  // warp-uniform broadcast
        if (g != cur) {
            atomicAdd(&g_pool[cur * 64 + tx], acc);
            if (tx == 0) atomicAdd(&g_gcnt[cur], c);
            acc = 0.0f; c = 0.0f; cur = g;
        }
        acc += B[i * 64 + tx];
        c += 1.0f;
    }
    atomicAdd(&g_pool[cur * 64 + tx], acc);
    if (tx == 0) atomicAdd(&g_gcnt[cur], c);
}

// (sums/cnt) @ Wl + bl  -> out[64,10]
__global__ void k_final(const float* __restrict__ Wl, const float* __restrict__ bl,
                        float* __restrict__ out) {
    int t = threadIdx.x;
    if (t >= NG * NC) return;
    int g = t / NC, c = t % NC;
    float cnt = fmaxf(g_gcnt[g], 1.0f);
    float s = 0.0f;
    #pragma unroll
    for (int k = 0; k < 64; k++)
        s += g_pool[g * 64 + k] * Wl[k * NC + c];
    out[t] = s / cnt + bl[c];
}

// ---------------------------------------------------------------------------
extern "C" void kernel_launch(void* const* d_in, const int* in_sizes, int n_in,
                              void* d_out, int out_size) {
    const float* x     = (const float*)d_in[0];
    const int*   ei    = (const int*)  d_in[1];   // [2, E]
    const int*   batch = (const int*)  d_in[2];
    const float* P     = (const float*)d_in[3];
    const float* W1 = (const float*)d_in[4];  const float* b1 = (const float*)d_in[5];
    const float* W2 = (const float*)d_in[6];  const float* b2 = (const float*)d_in[7];
    const float* W3 = (const float*)d_in[8];  const float* b3 = (const float*)d_in[9];
    const float* Wl = (const float*)d_in[10]; const float* bl = (const float*)d_in[11];
    const int* row = ei;
    const int* col = ei + N_EDGES;

    float *A, *Bv;
    cudaGetSymbolAddress((void**)&A,  g_A);
    cudaGetSymbolAddress((void**)&Bv, g_B);

    const int nb_n = (N_NODES + 255) / 256;
    const int nb_e = (N_EDGES + 255) / 256;
    const int nb_g = (N_NODES + 63) / 64;
    const int nb_a = (N_NODES + 7) / 8;

    k_init<<<nb_n, 256>>>();
    k_deg <<<nb_e, 256>>>(col, P);
    k_dis <<<nb_n, 256>>>();
    k_scan<<<1, 1024>>>();
    k_fill<<<nb_e, 256>>>(row, col, P);

    k_gemm<<<nb_g, 256>>>(x,  W1, A);
    k_agg <<<nb_a, 256>>>(A, Bv, b1, 1);
    k_gemm<<<nb_g, 256>>>(Bv, W2, A);
    k_agg <<<nb_a, 256>>>(A, Bv, b2, 1);
    k_gemm<<<nb_g, 256>>>(Bv, W3, A);
    k_agg <<<nb_a, 256>>>(A, Bv, b3, 0);

    k_pool <<<(N_NODES + 511) / 512, 64>>>(Bv, batch);
    k_final<<<1, 640>>>(Wl, bl, (float*)d_out);
}

// round 4
// speedup vs baseline: 1.5369x; 1.5369x over previous
#include <cuda_runtime.h>

#define N_NODES 50000
#define N_EDGES 800000
#define NF 64
#define NG 64
#define NC 10
#define NBLK 196   // ceil(50000/256)

// ---- scratch (static __device__, no runtime allocation) ----
__device__ float g_deg[N_NODES];
__device__ float g_dis[N_NODES];
__device__ int   g_ecnt[N_NODES];
__device__ int   g_off[N_NODES + 1];
__device__ int   g_cur[N_NODES];
__device__ int   g_bsum[256];
__device__ __align__(16) int2 g_edge[N_EDGES];     // (src_row, norm as bits)
__device__ __align__(256) float g_A[N_NODES * NF];
__device__ __align__(256) float g_B[N_NODES * NF];
__device__ float g_pool[NG * NF];
__device__ float g_gcnt[NG];

// ---------------------------------------------------------------------------
__global__ void k_init() {
    int i = blockIdx.x * blockDim.x + threadIdx.x;
    if (i < N_NODES) { g_deg[i] = 1.0f; g_ecnt[i] = 0; }   // self-loop weight 1
    if (i < NG * NF) g_pool[i] = 0.0f;
    if (i < NG)      g_gcnt[i] = 0.0f;
    if (i < 256)     g_bsum[i] = 0;
    if (i == 0)      g_off[N_NODES] = N_EDGES;             // total is constant
}

// degree accumulation (sigmoid edge weights) + in-degree histogram
__global__ void k_deg(const int* __restrict__ col, const float* __restrict__ P) {
    int e = blockIdx.x * blockDim.x + threadIdx.x;
    if (e >= N_EDGES) return;
    float w = 1.0f / (1.0f + expf(-P[e]));
    int c = col[e];
    atomicAdd(&g_deg[c], w);
    atomicAdd(&g_ecnt[c], 1);
}

// ---- 3-phase device-wide exclusive scan of g_ecnt -> g_off ----
__global__ void k_scan1() {                 // per-block local exclusive scan
    __shared__ int s[256];
    int t = threadIdx.x;
    int i = blockIdx.x * 256 + t;
    int v = (i < N_NODES) ? g_ecnt[i] : 0;
    int val = v;
    s[t] = val;
    __syncthreads();
    #pragma unroll
    for (int d = 1; d < 256; d <<= 1) {
        int add = (t >= d) ? s[t - d] : 0;
        __syncthreads();
        val += add;
        s[t] = val;
        __syncthreads();
    }
    if (i < N_NODES) g_off[i] = val - v;    // local exclusive
    if (t == 255)    g_bsum[blockIdx.x] = val;
}

__global__ void k_scan2() {                 // scan 196 block sums (1 block)
    __shared__ int s[256];
    int t = threadIdx.x;
    int v = g_bsum[t];                      // zero-padded by k_init
    int val = v;
    s[t] = val;
    __syncthreads();
    #pragma unroll
    for (int d = 1; d < 256; d <<= 1) {
        int add = (t >= d) ? s[t - d] : 0;
        __syncthreads();
        val += add;
        s[t] = val;
        __syncthreads();
    }
    g_bsum[t] = val - v;                    // exclusive block offsets
}

__global__ void k_scan3() {                 // add block offsets; fuse dis=rsqrt(deg)
    int i = blockIdx.x * 256 + threadIdx.x;
    if (i >= N_NODES) return;
    int o = g_off[i] + g_bsum[blockIdx.x];
    g_off[i] = o;
    g_cur[i] = o;
    g_dis[i] = rsqrtf(g_deg[i]);            // deg >= 1 always
}

// fill CSC: per incoming edge store interleaved (source row, norm coefficient)
__global__ void k_fill(const int* __restrict__ row, const int* __restrict__ col,
                       const float* __restrict__ P) {
    int e = blockIdx.x * blockDim.x + threadIdx.x;
    if (e >= N_EDGES) return;
    int r = row[e], c = col[e];
    float w  = 1.0f / (1.0f + expf(-P[e]));
    float nm = g_dis[r] * w * g_dis[c];
    int slot = atomicAdd(&g_cur[c], 1);
    g_edge[slot] = make_int2(r, __float_as_int(nm));
}

// out[n,64] = in[n,64] @ W[64,64]; W column register-resident, Is broadcast LDS.128
__global__ void k_gemm(const float* __restrict__ in, const float* __restrict__ W,
                       float* __restrict__ out) {
    __shared__ float Is[4][64];
    int tx = threadIdx.x & 63;
    int ty = threadIdx.x >> 6;
    float w[64];
    #pragma unroll
    for (int k = 0; k < 64; k++) w[k] = __ldg(&W[k * 64 + tx]);
    int base = blockIdx.x * 64;
    for (int rg = 0; rg < 16; rg++) {
        int r = base + rg * 4 + ty;
        float v = (r < N_NODES) ? in[r * 64 + tx] : 0.0f;
        __syncthreads();
        Is[ty][tx] = v;
        __syncthreads();
        float a0 = 0.f, a1 = 0.f, a2 = 0.f, a3 = 0.f;
        #pragma unroll
        for (int k = 0; k < 64; k += 4) {
            float4 iv = *(const float4*)&Is[ty][k];
            a0 = fmaf(iv.x, w[k],     a0);
            a1 = fmaf(iv.y, w[k + 1], a1);
            a2 = fmaf(iv.z, w[k + 2], a2);
            a3 = fmaf(iv.w, w[k + 3], a3);
        }
        if (r < N_NODES) out[r * 64 + tx] = (a0 + a1) + (a2 + a3);
    }
}

// warp-per-node gather SpMM: B[c] = selfnorm*A[c] + sum_e norm_e * A[src_e] + bias
__global__ void k_agg(const float* __restrict__ A, float* __restrict__ B,
                      const float* __restrict__ bias, int do_relu) {
    int node = blockIdx.x * 8 + (threadIdx.x >> 5);
    if (node >= N_NODES) return;
    int lane = threadIdx.x & 31;
    const float2* Ar = (const float2*)A;

    float d  = g_dis[node];
    float sn = d * d;                     // self-loop coefficient
    float2 hv = __ldg(&Ar[node * 32 + lane]);
    float ax = sn * hv.x, ay = sn * hv.y;

    int s = g_off[node], e = g_off[node + 1];
    int i = s;
    int e4 = s + ((e - s) & ~3);
    for (; i < e4; i += 4) {              // 4x unroll for MLP across L2 latency
        int2 e0 = g_edge[i],   e1 = g_edge[i + 1];
        int2 e2 = g_edge[i + 2], e3 = g_edge[i + 3];
        float2 h0 = __ldg(&Ar[e0.x * 32 + lane]);
        float2 h1 = __ldg(&Ar[e1.x * 32 + lane]);
        float2 h2 = __ldg(&Ar[e2.x * 32 + lane]);
        float2 h3 = __ldg(&Ar[e3.x * 32 + lane]);
        float n0 = __int_as_float(e0.y), n1 = __int_as_float(e1.y);
        float n2 = __int_as_float(e2.y), n3 = __int_as_float(e3.y);
        ax += n0 * h0.x + n1 * h1.x + n2 * h2.x + n3 * h3.x;
        ay += n0 * h0.y + n1 * h1.y + n2 * h2.y + n3 * h3.y;
    }
    for (; i < e; i++) {
        int2 ed = g_edge[i];
        float nm = __int_as_float(ed.y);
        float2 h = __ldg(&Ar[ed.x * 32 + lane]);
        ax += nm * h.x;
        ay += nm * h.y;
    }
    float2 bb = ((const float2*)bias)[lane];
    ax += bb.x; ay += bb.y;
    if (do_relu) { ax = fmaxf(ax, 0.0f); ay = fmaxf(ay, 0.0f); }
    ((float2*)B)[node * 32 + lane] = make_float2(ax, ay);
}

// segment mean pool: exploit sorted batch — run-length accumulate, few atomics
__global__ void k_pool(const float* __restrict__ B, const int* __restrict__ batch) {
    int tx = threadIdx.x;                  // 64 threads = 64 features
    int start = blockIdx.x * 512;
    if (start >= N_NODES) return;
    int end = min(start + 512, N_NODES);
    int cur = batch[start];
    float acc = 0.0f, c = 0.0f;
    for (int i = start; i < end; i++) {
        int g = batch[i];                  // warp-uniform broadcast
        if (g != cur) {
            atomicAdd(&g_pool[cur * 64 + tx], acc);
            if (tx == 0) atomicAdd(&g_gcnt[cur], c);
            acc = 0.0f; c = 0.0f; cur = g;
        }
        acc += B[i * 64 + tx];
        c += 1.0f;
    }
    atomicAdd(&g_pool[cur * 64 + tx], acc);
    if (tx == 0) atomicAdd(&g_gcnt[cur], c);
}

// (sums/cnt) @ Wl + bl  -> out[64,10]
__global__ void k_final(const float* __restrict__ Wl, const float* __restrict__ bl,
                        float* __restrict__ out) {
    int t = threadIdx.x;
    if (t >= NG * NC) return;
    int g = t / NC, c = t % NC;
    float cnt = fmaxf(g_gcnt[g], 1.0f);
    float s = 0.0f;
    #pragma unroll
    for (int k = 0; k < 64; k++)
        s += g_pool[g * 64 + k] * Wl[k * NC + c];
    out[t] = s / cnt + bl[c];
}

// ---------------------------------------------------------------------------
extern "C" void kernel_launch(void* const* d_in, const int* in_sizes, int n_in,
                              void* d_out, int out_size) {
    const float* x     = (const float*)d_in[0];
    const int*   ei    = (const int*)  d_in[1];   // [2, E]
    const int*   batch = (const int*)  d_in[2];
    const float* P     = (const float*)d_in[3];
    const float* W1 = (const float*)d_in[4];  const float* b1 = (const float*)d_in[5];
    const float* W2 = (const float*)d_in[6];  const float* b2 = (const float*)d_in[7];
    const float* W3 = (const float*)d_in[8];  const float* b3 = (const float*)d_in[9];
    const float* Wl = (const float*)d_in[10]; const float* bl = (const float*)d_in[11];
    const int* row = ei;
    const int* col = ei + N_EDGES;

    float *A, *Bv;
    cudaGetSymbolAddress((void**)&A,  g_A);
    cudaGetSymbolAddress((void**)&Bv, g_B);

    const int nb_e = (N_EDGES + 255) / 256;
    const int nb_g = (N_NODES + 63) / 64;
    const int nb_a = (N_NODES + 7) / 8;

    k_init <<<NBLK, 256>>>();
    k_deg  <<<nb_e, 256>>>(col, P);
    k_scan1<<<NBLK, 256>>>();
    k_scan2<<<1, 256>>>();
    k_scan3<<<NBLK, 256>>>();
    k_fill <<<nb_e, 256>>>(row, col, P);

    k_gemm<<<nb_g, 256>>>(x,  W1, A);
    k_agg <<<nb_a, 256>>>(A, Bv, b1, 1);
    k_gemm<<<nb_g, 256>>>(Bv, W2, A);
    k_agg <<<nb_a, 256>>>(A, Bv, b2, 1);
    k_gemm<<<nb_g, 256>>>(Bv, W3, A);
    k_agg <<<nb_a, 256>>>(A, Bv, b3, 0);

    k_pool <<<(N_NODES + 511) / 512, 64>>>(Bv, batch);
    k_final<<<1, 640>>>(Wl, bl, (float*)d_out);
}